// round 5
// baseline (speedup 1.0000x reference)
#include <cuda_runtime.h>
#include <cuda_bf16.h>
#include <mma.h>
#include <math.h>

using namespace nvcuda;

#define HIDDEN 128
#define MAX_ING 20000
#define MAX_CMP 10000

// Precomputed per-node projections in bf16 (L2-resident: 5MB + 2.5MB)
__device__ __nv_bfloat16 g_P_ing[MAX_ING * HIDDEN];
__device__ __nv_bfloat16 g_P_cmp[MAX_CMP * HIDDEN];

// Split-bf16 copies of W1 (256x128): W ~= W_hi + W_lo
__device__ __nv_bfloat16 g_Whi[2 * HIDDEN * HIDDEN];
__device__ __nv_bfloat16 g_Wlo[2 * HIDDEN * HIDDEN];

// ---------------------------------------------------------------------------
// Prep: split W1 into bf16 hi/lo parts (32768 elements, trivial)
// ---------------------------------------------------------------------------
__global__ void prep_kernel(const float* __restrict__ W1)
{
    const int idx = blockIdx.x * blockDim.x + threadIdx.x;
    if (idx >= 2 * HIDDEN * HIDDEN) return;
    const float w = W1[idx];
    const __nv_bfloat16 hi = __float2bfloat16_rn(w);
    const __nv_bfloat16 lo = __float2bfloat16_rn(w - __bfloat162float(hi));
    g_Whi[idx] = hi;
    g_Wlo[idx] = lo;
}

// ---------------------------------------------------------------------------
// Tensor-core projection: P = X @ W (+bias for cmp), fp32-exact via
// split-bf16: x_hi*W_hi + x_hi*W_lo + x_lo*W_hi  (x_lo*W_lo ~ 2e-5, dropped).
// Block: 256 threads (8 warps), 64 rows x 128 cols of output.
// Warp (r,c) grid 4x2: each warp does 16 rows x 64 cols = 4 wmma acc frags.
// ---------------------------------------------------------------------------
#define A_LD 136   // smem leading dim for A tiles (272B, mult of 16B, conflict-stagger)

__global__ void __launch_bounds__(256) proj_kernel(
    const float* __restrict__ x_ing,
    const float* __restrict__ x_cmp,
    const float* __restrict__ b1,
    int n_ing, int n_cmp, int blocks_ing)
{
    const bool is_cmp = (blockIdx.x >= blocks_ing);
    const float* __restrict__ X = is_cmp ? x_cmp : x_ing;
    __nv_bfloat16* __restrict__ P = is_cmp ? g_P_cmp : g_P_ing;
    const int nrows = is_cmp ? n_cmp : n_ing;
    const int bid = is_cmp ? (blockIdx.x - blocks_ing) : blockIdx.x;
    const int woff = is_cmp ? (HIDDEN * HIDDEN) : 0;

    const int row0 = bid * 64;
    const int tid = threadIdx.x;
    const int wid = tid >> 5;

    // 34816B shared: phase 1 = A_hi/A_lo bf16 tiles; phase 2 = fp32 staging
    __shared__ __align__(16) float smem_f[8704];
    __nv_bfloat16* A_hi = reinterpret_cast<__nv_bfloat16*>(smem_f);
    __nv_bfloat16* A_lo = A_hi + 64 * A_LD;

    // --- load X tile (64x128 fp32) and split into bf16 hi/lo ---
    const float4* __restrict__ X4 = reinterpret_cast<const float4*>(X);
    #pragma unroll
    for (int i = 0; i < 8; i++) {
        const int v = tid + i * 256;          // 2048 float4 slots
        const int r = v >> 5;                 // 0..63
        const int c4 = v & 31;                // float4 within row
        const int rs = min(row0 + r, nrows - 1);
        const float4 x = X4[(size_t)rs * 32 + c4];

        __nv_bfloat16 h[4], l[4];
        const float xf[4] = {x.x, x.y, x.z, x.w};
        #pragma unroll
        for (int j = 0; j < 4; j++) {
            h[j] = __float2bfloat16_rn(xf[j]);
            l[j] = __float2bfloat16_rn(xf[j] - __bfloat162float(h[j]));
        }
        *reinterpret_cast<uint2*>(&A_hi[r * A_LD + c4 * 4]) = *reinterpret_cast<uint2*>(h);
        *reinterpret_cast<uint2*>(&A_lo[r * A_LD + c4 * 4]) = *reinterpret_cast<uint2*>(l);
    }
    __syncthreads();

    // --- wmma mainloop ---
    const int warp_r = (wid & 3) * 16;
    const int warp_c = (wid >> 2) * 64;

    wmma::fragment<wmma::accumulator, 16, 16, 16, float> acc[4];
    #pragma unroll
    for (int c = 0; c < 4; c++) wmma::fill_fragment(acc[c], 0.f);

    const __nv_bfloat16* Bhi = g_Whi + woff;
    const __nv_bfloat16* Blo = g_Wlo + woff;

    #pragma unroll
    for (int k = 0; k < 8; k++) {
        wmma::fragment<wmma::matrix_a, 16, 16, 16, __nv_bfloat16, wmma::row_major> a_hi, a_lo;
        wmma::load_matrix_sync(a_hi, &A_hi[warp_r * A_LD + k * 16], A_LD);
        wmma::load_matrix_sync(a_lo, &A_lo[warp_r * A_LD + k * 16], A_LD);

        #pragma unroll
        for (int c = 0; c < 4; c++) {
            const int col = warp_c + c * 16;
            wmma::fragment<wmma::matrix_b, 16, 16, 16, __nv_bfloat16, wmma::row_major> b_hi, b_lo;
            wmma::load_matrix_sync(b_hi, Bhi + (k * 16) * HIDDEN + col, HIDDEN);
            wmma::load_matrix_sync(b_lo, Blo + (k * 16) * HIDDEN + col, HIDDEN);
            wmma::mma_sync(acc[c], a_hi, b_hi, acc[c]);
            wmma::mma_sync(acc[c], a_hi, b_lo, acc[c]);
            wmma::mma_sync(acc[c], a_lo, b_hi, acc[c]);
        }
    }

    // --- stage fp32 results in shared (reuse A tile memory) ---
    __syncthreads();
    #pragma unroll
    for (int c = 0; c < 4; c++)
        wmma::store_matrix_sync(&smem_f[warp_r * 128 + warp_c + c * 16], acc[c],
                                128, wmma::mem_row_major);
    __syncthreads();

    // --- bias (cmp only) + convert to bf16 + store ---
    uint2* P2 = reinterpret_cast<uint2*>(P);
    #pragma unroll
    for (int i = 0; i < 8; i++) {
        const int v = tid + i * 256;
        const int r = v >> 5;
        const int c4 = v & 31;
        if (row0 + r < nrows) {
            float4 p = *reinterpret_cast<const float4*>(&smem_f[r * 128 + c4 * 4]);
            if (is_cmp) {
                const float4 bv = reinterpret_cast<const float4*>(b1)[c4];
                p.x += bv.x; p.y += bv.y; p.z += bv.z; p.w += bv.w;
            }
            __nv_bfloat162 lo = __float22bfloat162_rn(make_float2(p.x, p.y));
            __nv_bfloat162 hi = __float22bfloat162_rn(make_float2(p.z, p.w));
            uint2 o;
            o.x = *reinterpret_cast<unsigned int*>(&lo);
            o.y = *reinterpret_cast<unsigned int*>(&hi);
            P2[(size_t)(row0 + r) * 32 + c4] = o;
        }
    }
}

// ---------------------------------------------------------------------------
// Edge kernel (unchanged from R4): 8 lanes/edge, 4 edges/group, contiguous
// 128B-line group loads, packed bf16 add+relu, fp32 dot, 3-shuffle reduce.
// ---------------------------------------------------------------------------
__device__ __forceinline__ float edge_slice_dot(
    int s, int d, int t,
    const float4 wl0, const float4 wl1,
    const float4 wh0, const float4 wh1)
{
    const char* pa = (const char*)g_P_ing + (size_t)s * 256 + t * 16;
    const char* pb = (const char*)g_P_cmp + (size_t)d * 256 + t * 16;
    const uint4 al = *reinterpret_cast<const uint4*>(pa);
    const uint4 ah = *reinterpret_cast<const uint4*>(pa + 128);
    const uint4 bl = *reinterpret_cast<const uint4*>(pb);
    const uint4 bh = *reinterpret_cast<const uint4*>(pb + 128);

    const __nv_bfloat162 z2 = __float2bfloat162_rn(0.f);

    const unsigned av[8] = {al.x, al.y, al.z, al.w, ah.x, ah.y, ah.z, ah.w};
    const unsigned bv[8] = {bl.x, bl.y, bl.z, bl.w, bh.x, bh.y, bh.z, bh.w};
    const float wv[16] = {wl0.x, wl0.y, wl0.z, wl0.w,
                          wl1.x, wl1.y, wl1.z, wl1.w,
                          wh0.x, wh0.y, wh0.z, wh0.w,
                          wh1.x, wh1.y, wh1.z, wh1.w};

    float acc = 0.f;
    #pragma unroll
    for (int j = 0; j < 8; j++) {
        __nv_bfloat162 ha = *reinterpret_cast<const __nv_bfloat162*>(&av[j]);
        __nv_bfloat162 hb = *reinterpret_cast<const __nv_bfloat162*>(&bv[j]);
        __nv_bfloat162 h = __hmax2(__hadd2(ha, hb), z2);
        float2 f = __bfloat1622float2(h);
        acc = fmaf(f.x, wv[2 * j], acc);
        acc = fmaf(f.y, wv[2 * j + 1], acc);
    }
    return acc;
}

__global__ void __launch_bounds__(256) edge_kernel(
    const int* __restrict__ ei,
    const float* __restrict__ W2,
    const float* __restrict__ b2,
    float* __restrict__ out,
    int E)
{
    const int gid = (blockIdx.x * 256 + threadIdx.x) >> 3;
    const int t = threadIdx.x & 7;
    const int e0 = gid * 4;
    if (e0 >= E) return;

    const float4* W24 = reinterpret_cast<const float4*>(W2);
    const float4 wl0 = __ldg(W24 + 2 * t + 0);
    const float4 wl1 = __ldg(W24 + 2 * t + 1);
    const float4 wh0 = __ldg(W24 + 16 + 2 * t + 0);
    const float4 wh1 = __ldg(W24 + 16 + 2 * t + 1);
    const float b2v = __ldg(b2);

    int sv[4], dv[4];
    int ne;
    if (e0 + 4 <= E) {
        ne = 4;
        const int4 s4 = __ldg(reinterpret_cast<const int4*>(ei + e0));
        const int4 d4 = __ldg(reinterpret_cast<const int4*>(ei + E + e0));
        sv[0] = s4.x; sv[1] = s4.y; sv[2] = s4.z; sv[3] = s4.w;
        dv[0] = d4.x; dv[1] = d4.y; dv[2] = d4.z; dv[3] = d4.w;
    } else {
        ne = E - e0;
        for (int i = 0; i < ne; i++) {
            sv[i] = __ldg(ei + e0 + i);
            dv[i] = __ldg(ei + E + e0 + i);
        }
        for (int i = ne; i < 4; i++) { sv[i] = 0; dv[i] = 0; }
    }

    float acc[4];
    #pragma unroll
    for (int i = 0; i < 4; i++)
        acc[i] = edge_slice_dot(sv[i], dv[i], t, wl0, wl1, wh0, wh1);

    #pragma unroll
    for (int i = 0; i < 4; i++) {
        acc[i] += __shfl_xor_sync(0xFFFFFFFFu, acc[i], 1);
        acc[i] += __shfl_xor_sync(0xFFFFFFFFu, acc[i], 2);
        acc[i] += __shfl_xor_sync(0xFFFFFFFFu, acc[i], 4);
    }

    if (t == 0) {
        #pragma unroll
        for (int i = 0; i < 4; i++) {
            if (i < ne) {
                const float z = acc[i] + b2v;
                out[e0 + i] = 1.f / (1.f + __expf(-z));
            }
        }
    }
}

extern "C" void kernel_launch(void* const* d_in, const int* in_sizes, int n_in,
                              void* d_out, int out_size)
{
    const float* x_ing = (const float*)d_in[0];
    const float* x_cmp = (const float*)d_in[1];
    const int*   ei    = (const int*)d_in[2];
    const float* W1    = (const float*)d_in[3];
    const float* b1    = (const float*)d_in[4];
    const float* W2    = (const float*)d_in[5];
    const float* b2    = (const float*)d_in[6];
    float* out = (float*)d_out;

    const int n_ing = in_sizes[0] / HIDDEN;
    const int n_cmp = in_sizes[1] / HIDDEN;
    const int E     = in_sizes[2] / 2;

    prep_kernel<<<(2 * HIDDEN * HIDDEN + 255) / 256, 256>>>(W1);

    const int blocks_ing = (n_ing + 63) / 64;
    const int blocks_cmp = (n_cmp + 63) / 64;
    proj_kernel<<<blocks_ing + blocks_cmp, 256>>>(x_ing, x_cmp, b1,
                                                  n_ing, n_cmp, blocks_ing);

    const int blocks = (E + 127) / 128;  // 128 edges per 256-thread block
    edge_kernel<<<blocks, 256>>>(ei, W2, b2, out, E);
}